// round 13
// baseline (speedup 1.0000x reference)
#include <cuda_runtime.h>
#include <cuda_fp16.h>
#include <cstdint>

#define N_USERS 50000
#define D 128
#define N_EDGES 800000
#define E_PER_WARP 8
#define AS_STRIDE 132          // padded smem stride in floats (conflict-free)

// -------- device scratch (no cudaMalloc allowed) --------
__device__ __half g_weighted_h[N_USERS * D];   // weighted = emb @ W in fp16

// ---------------------------------------------------------------------------
// Kernel 1: weighted_h = fp16(user_emb @ W) via tf32 mma.sync; out = user_emb.
// Block = 256 threads (8 warps), 128 rows per block.
// Phase 0: W -> smem (linear, coalesced, padded stride)
// Phase 1: in-smem permute into MMA B-fragment order (tf32-rounded)
// Phase 2: A tile -> smem (tf32-pre-rounded) + fused residual copy
// Mainloop: per warp/kk: 4 conflict-free LDS + 16 conflict-free LDS.64 + 16 MMA.
// ---------------------------------------------------------------------------
__global__ __launch_bounds__(256) void gemm_kernel(
    const float* __restrict__ emb,
    const float* __restrict__ W,    // [D, D] fp32 row-major
    __half* __restrict__ wout,      // [N_USERS, D] fp16
    float* __restrict__ resout)     // [N_USERS, D] fp32 residual init
{
    extern __shared__ float smemf[];
    float*  As  = smemf;                                       // [128 * AS_STRIDE]
    float2* Wps = reinterpret_cast<float2*>(smemf + 128 * AS_STRIDE);  // [8192]

    const int tid = threadIdx.x;
    const int rowbase = blockIdx.x * 128;

    // ---- Phase 0: W -> As (linear, coalesced float4, stride 33 f4) ----
    {
        const float4* Wg4 = reinterpret_cast<const float4*>(W);
        float4* As4 = reinterpret_cast<float4*>(As);
        #pragma unroll
        for (int i = 0; i < 16; i++) {              // 128 rows * 32 float4
            int idx = i * 256 + tid;
            int r = idx >> 5;
            int q = idx & 31;
            As4[r * (AS_STRIDE / 4) + q] = Wg4[r * 32 + q];
        }
    }
    __syncthreads();

    // ---- Phase 1: permute W (smem) -> Wps in B-fragment order, tf32 ----
    // Wps[(kk*16+j)*32 + lane] = { tf32(W[8kk+c][8j+g]), tf32(W[8kk+c+4][8j+g]) }
    #pragma unroll
    for (int i = 0; i < 32; i++) {                  // 8192 float2 entries
        int idx  = i * 256 + tid;
        int lane = idx & 31;
        int j    = (idx >> 5) & 15;
        int kk   = idx >> 9;
        int cc   = lane & 3;
        int gg   = lane >> 2;
        int col  = j * 8 + gg;
        float w0 = As[(kk * 8 + cc) * AS_STRIDE + col];
        float w1 = As[(kk * 8 + cc + 4) * AS_STRIDE + col];
        float2 t;
        asm("cvt.rna.tf32.f32 %0, %1;" : "=f"(t.x) : "f"(w0));
        asm("cvt.rna.tf32.f32 %0, %1;" : "=f"(t.y) : "f"(w1));
        Wps[idx] = t;
    }
    __syncthreads();

    // ---- Phase 2: A tile -> As (tf32-rounded) + fused residual out = emb ----
    {
        const float4* src = reinterpret_cast<const float4*>(emb);
        float4* dst = reinterpret_cast<float4*>(resout);
        float4* As4 = reinterpret_cast<float4*>(As);
        #pragma unroll
        for (int i = 0; i < 16; i++) {              // 128 rows * 32 float4
            int idx = i * 256 + tid;
            int r = idx >> 5;
            int q = idx & 31;
            int gr = min(rowbase + r, N_USERS - 1);
            float4 v = src[(size_t)gr * 32 + q];
            if (rowbase + r < N_USERS)
                dst[(size_t)(rowbase + r) * 32 + q] = v;   // exact residual
            float4 t;
            asm("cvt.rna.tf32.f32 %0, %1;" : "=f"(t.x) : "f"(v.x));
            asm("cvt.rna.tf32.f32 %0, %1;" : "=f"(t.y) : "f"(v.y));
            asm("cvt.rna.tf32.f32 %0, %1;" : "=f"(t.z) : "f"(v.z));
            asm("cvt.rna.tf32.f32 %0, %1;" : "=f"(t.w) : "f"(v.w));
            As4[r * (AS_STRIDE / 4) + q] = t;
        }
    }
    __syncthreads();

    const int warp = tid >> 5;
    const int lane = tid & 31;
    const int gid  = lane >> 2;     // 0..7
    const int c    = lane & 3;      // 0..3

    const int trA = warp * 16 + gid;
    const int trB = warp * 16 + gid + 8;
    const int rA = rowbase + trA;
    const int rB = rowbase + trB;
    const float* pA = As + trA * AS_STRIDE;
    const float* pB = As + trB * AS_STRIDE;

    float acc[16][4];
    #pragma unroll
    for (int j = 0; j < 16; j++)
        #pragma unroll
        for (int q = 0; q < 4; q++) acc[j][q] = 0.f;

    #pragma unroll 1
    for (int kk = 0; kk < 16; kk++) {
        const int k0 = kk * 8;
        // A fragment already tf32-rounded (conflict-free banks)
        unsigned a0 = __float_as_uint(pA[k0 + c]);
        unsigned a1 = __float_as_uint(pB[k0 + c]);
        unsigned a2 = __float_as_uint(pA[k0 + c + 4]);
        unsigned a3 = __float_as_uint(pB[k0 + c + 4]);

        const float2* wrow = Wps + kk * 16 * 32 + lane;
        #pragma unroll
        for (int j = 0; j < 16; j++) {
            float2 bp = wrow[j * 32];               // one LDS.64, conflict-free
            unsigned b0 = __float_as_uint(bp.x);
            unsigned b1 = __float_as_uint(bp.y);
            asm volatile(
                "mma.sync.aligned.m16n8k8.row.col.f32.tf32.tf32.f32 "
                "{%0,%1,%2,%3}, {%4,%5,%6,%7}, {%8,%9}, {%0,%1,%2,%3};"
                : "+f"(acc[j][0]), "+f"(acc[j][1]), "+f"(acc[j][2]), "+f"(acc[j][3])
                : "r"(a0), "r"(a1), "r"(a2), "r"(a3), "r"(b0), "r"(b1));
        }
    }

    // ---- epilogue: fp16 weighted ----
    #pragma unroll
    for (int j = 0; j < 16; j++) {
        const int col = j * 8 + 2 * c;
        __half2 hA = __floats2half2_rn(acc[j][0], acc[j][1]);
        __half2 hB = __floats2half2_rn(acc[j][2], acc[j][3]);
        if (rA < N_USERS) *reinterpret_cast<__half2*>(wout + (size_t)rA * D + col) = hA;
        if (rB < N_USERS) *reinterpret_cast<__half2*>(wout + (size_t)rB * D + col) = hB;
    }
}

// ---------------------------------------------------------------------------
// Kernel 2: out[rows[e]] += vals[e] * weighted_h[cols[e]]
// 8 edges per warp: lanes 0-7 hold metadata, 8 gathers in flight, 8 REDs.
// 800000 = 100000 warps * 8 exactly; no tail.
// ---------------------------------------------------------------------------
__global__ __launch_bounds__(256) void edge_kernel(
    const int* __restrict__ rows,
    const int* __restrict__ cols,
    const float* __restrict__ vals,
    const __half* __restrict__ weighted,
    float* __restrict__ out)
{
    const int warp = (blockIdx.x * blockDim.x + threadIdx.x) >> 5;
    const int lane = threadIdx.x & 31;
    const long long e0 = (long long)warp * E_PER_WARP;
    if (e0 >= N_EDGES) return;

    const int eidx = (int)e0 + (lane & (E_PER_WARP - 1));
    int   ri = __ldg(rows + eidx);
    int   ci = __ldg(cols + eidx);
    float vi = __ldg(vals + eidx);

    uint2 pk[E_PER_WARP];
    #pragma unroll
    for (int i = 0; i < E_PER_WARP; i++) {
        int cc = __shfl_sync(0xffffffffu, ci, i);
        pk[i] = *reinterpret_cast<const uint2*>(weighted + (size_t)cc * D + lane * 4);
    }

    #pragma unroll
    for (int i = 0; i < E_PER_WARP; i++) {
        int   r = __shfl_sync(0xffffffffu, ri, i);
        float v = __shfl_sync(0xffffffffu, vi, i);
        __half2 h0 = *reinterpret_cast<__half2*>(&pk[i].x);
        __half2 h1 = *reinterpret_cast<__half2*>(&pk[i].y);
        float2 f0 = __half22float2(h0);
        float2 f1 = __half22float2(h1);
        float px = v * f0.x, py = v * f0.y, pz = v * f1.x, pw = v * f1.y;
        float* dst = out + (size_t)r * D + lane * 4;
        asm volatile("red.global.add.v4.f32 [%0], {%1,%2,%3,%4};"
                     :: "l"(dst), "f"(px), "f"(py), "f"(pz), "f"(pw)
                     : "memory");
    }
}

// ---------------------------------------------------------------------------
// Launch
// ---------------------------------------------------------------------------
extern "C" void kernel_launch(void* const* d_in, const int* in_sizes, int n_in,
                              void* d_out, int out_size)
{
    const float* user_emb = (const float*)d_in[0];
    const float* social_w = (const float*)d_in[1];
    const int*   rows     = (const int*)d_in[2];
    const int*   cols     = (const int*)d_in[3];
    const float* vals     = (const float*)d_in[4];
    float*       out      = (float*)d_out;

    __half* weighted;  cudaGetSymbolAddress((void**)&weighted, g_weighted_h);

    // 1. GEMM (tf32 tensor cores) + in-smem W pack + fused residual init
    {
        const int smem_bytes = 128 * AS_STRIDE * sizeof(float)
                             + 16 * 16 * 32 * sizeof(float2);   // 67584 + 65536
        cudaFuncSetAttribute(gemm_kernel,
                             cudaFuncAttributeMaxDynamicSharedMemorySize, smem_bytes);
        int nblk = (N_USERS + 127) / 128;                       // 391
        gemm_kernel<<<nblk, 256, smem_bytes>>>(user_emb, social_w, weighted, out);
    }

    // 2. scatter-add edges, 8 edges per warp
    {
        int nwarps = N_EDGES / E_PER_WARP;              // 100000
        int nblk = (nwarps * 32 + 255) / 256;           // 12500
        edge_kernel<<<nblk, 256>>>(rows, cols, vals, weighted, out);
    }
}